// round 3
// baseline (speedup 1.0000x reference)
#include <cuda_runtime.h>

// ConvCapsuleLayer: B=2, H=W=48, IN_CAPS=8, ATOMS=16, KER=3, OUT_CAPS=16, ROUTINGS=3
// Ho=Wo=46, N = 2*46*46 = 4232 positions. One CTA per position, 256 threads.
//
// Algebraic restructure (no votes materialization):
//   votes[ki,o] = pose[ki] @ W[i,o]            (4x4 matrices)
//   s[o]        = sum_i ( sum_k coup[k,i,o]*pose[k,i] ) @ W[i,o]
//   logit_upd[ki,o] = sum_{a,b} pose[ki][a,b] * Q[i,o][a,b],
//       Q[i,o][a,b] = sum_c W[i,o][b,c] * v[o][a,c]

#define HH 48
#define WW 48
#define CIN 136          // IN_CAPS*(ATOMS+1)
#define HO 46
#define WO 46
#define KKI 72           // 9 * 8
#define NOUT 16
#define NTHREADS 256
#define ROUTINGS 3

__global__ __launch_bounds__(NTHREADS, 1)
void capsule_kernel(const float* __restrict__ x,
                    const float* __restrict__ Wg,
                    float* __restrict__ out)
{
    __shared__ __align__(16) float W_s[8 * 16 * 16];     // [i][o][b*4+c]
    __shared__ __align__(16) float pose_s[KKI * 16];     // [ki][a*4+b]
    __shared__ __align__(16) float act_s[KKI];
    __shared__ __align__(16) float logits[KKI * NOUT];   // [ki][o]
    __shared__ __align__(16) float coup[KKI * NOUT];     // [ki][o]
    __shared__ __align__(16) float PQ[2048];             // P: [o][i][16] / Q: [i][o][16]
    __shared__ __align__(16) float s_s[NOUT * 16];       // [o][a*4+c]
    __shared__ __align__(16) float v_s[NOUT * 16];       // [o][a*4+c]

    const int tid = threadIdx.x;
    const int n   = blockIdx.x;
    const int b   = n / (HO * WO);
    const int rem = n % (HO * WO);
    const int ho  = rem / WO;
    const int wo  = rem % WO;

    // ---- load W (2048 floats) ----
    #pragma unroll
    for (int idx = tid; idx < 2048; idx += NTHREADS)
        W_s[idx] = Wg[idx];

    // ---- load pose + act: 72 capsules x 17 values ----
    for (int idx = tid; idx < KKI * 17; idx += NTHREADS) {
        int ki = idx / 17;
        int a  = idx - ki * 17;
        int k  = ki >> 3;
        int i  = ki & 7;
        int di = k / 3;
        int dj = k - di * 3;
        float val = x[(size_t)(((b * HH + ho + di) * WW) + (wo + dj)) * CIN + i * 17 + a];
        if (a < 16) pose_s[ki * 16 + a] = val;
        else        act_s[ki] = val;
    }
    for (int idx = tid; idx < KKI * NOUT; idx += NTHREADS)
        logits[idx] = 0.0f;
    __syncthreads();

    float vout = 0.0f;  // this thread's final v value (o = tid>>4, e = tid&15)

    #pragma unroll 1
    for (int r = 0; r < ROUTINGS; r++) {
        // ---- A: coup[ki][o] = softmax_o(logits[ki]) * act[ki] ----
        if (tid < KKI) {
            const float* lrow = &logits[tid * 16];
            float m = lrow[0];
            #pragma unroll
            for (int o = 1; o < 16; o++) m = fmaxf(m, lrow[o]);
            float e[16];
            float sum = 0.0f;
            #pragma unroll
            for (int o = 0; o < 16; o++) { e[o] = __expf(lrow[o] - m); sum += e[o]; }
            float scale = act_s[tid] / sum;
            #pragma unroll
            for (int o = 0; o < 16; o++) coup[tid * 16 + o] = e[o] * scale;
        }
        __syncthreads();

        // ---- B: P[o][i][e] = sum_k coup[(k*8+i)][o] * pose[(k*8+i)][e] ----
        {
            int pair = tid >> 1;          // 0..127
            int o    = pair >> 3;
            int i    = pair & 7;
            int half = tid & 1;           // e in [half*8, half*8+8)
            float4 a0 = make_float4(0.f, 0.f, 0.f, 0.f);
            float4 a1 = make_float4(0.f, 0.f, 0.f, 0.f);
            #pragma unroll
            for (int k = 0; k < 9; k++) {
                int ki  = k * 8 + i;
                float c = coup[ki * 16 + o];
                const float4* pr = (const float4*)&pose_s[ki * 16 + half * 8];
                float4 p0 = pr[0], p1 = pr[1];
                a0.x += c * p0.x; a0.y += c * p0.y; a0.z += c * p0.z; a0.w += c * p0.w;
                a1.x += c * p1.x; a1.y += c * p1.y; a1.z += c * p1.z; a1.w += c * p1.w;
            }
            float4* dst = (float4*)&PQ[(o * 8 + i) * 16 + half * 8];
            dst[0] = a0; dst[1] = a1;
        }
        __syncthreads();

        // ---- C: s[o][a*4+c] = sum_i sum_b P[o][i][a*4+b] * W[i][o][b*4+c] ----
        if (tid < 64) {
            int o = tid >> 2, a = tid & 3;
            float4 acc = make_float4(0.f, 0.f, 0.f, 0.f);
            #pragma unroll
            for (int i = 0; i < 8; i++) {
                float4 p = *(const float4*)&PQ[(o * 8 + i) * 16 + a * 4];
                const float4* wr = (const float4*)&W_s[(i * 16 + o) * 16];
                float4 w0 = wr[0], w1 = wr[1], w2 = wr[2], w3 = wr[3];
                acc.x += p.x * w0.x + p.y * w1.x + p.z * w2.x + p.w * w3.x;
                acc.y += p.x * w0.y + p.y * w1.y + p.z * w2.y + p.w * w3.y;
                acc.z += p.x * w0.z + p.y * w1.z + p.z * w2.z + p.w * w3.z;
                acc.w += p.x * w0.w + p.y * w1.w + p.z * w2.w + p.w * w3.w;
            }
            *(float4*)&s_s[o * 16 + a * 4] = acc;
        }
        __syncthreads();

        // ---- D: squash. Each thread owns (o = tid>>4, e = tid&15) ----
        {
            int o = tid >> 4, e = tid & 15;
            const float4* sr = (const float4*)&s_s[o * 16];
            float4 s0 = sr[0], s1 = sr[1], s2 = sr[2], s3 = sr[3];
            float sq = s0.x*s0.x + s0.y*s0.y + s0.z*s0.z + s0.w*s0.w
                     + s1.x*s1.x + s1.y*s1.y + s1.z*s1.z + s1.w*s1.w
                     + s2.x*s2.x + s2.y*s2.y + s2.z*s2.z + s2.w*s2.w
                     + s3.x*s3.x + s3.y*s3.y + s3.z*s3.z + s3.w*s3.w;
            float se    = s_s[o * 16 + e];
            float scale = (sq / (1.0f + sq)) * rsqrtf(sq + 1e-7f);
            vout = se * scale;
            v_s[tid] = vout;
        }
        if (r == ROUTINGS - 1) break;
        __syncthreads();

        // ---- E: Q[i][o][a*4+b] = sum_c v[o][a*4+c] * W[i][o][b*4+c] ----
        {
            int io   = tid >> 1;          // 0..127
            int i    = io >> 4;
            int o    = io & 15;
            int half = tid & 1;           // a in {half*2, half*2+1}
            const float4* wr = (const float4*)&W_s[(i * 16 + o) * 16];
            float4 w0 = wr[0], w1 = wr[1], w2 = wr[2], w3 = wr[3];
            #pragma unroll
            for (int aa = 0; aa < 2; aa++) {
                int a = half * 2 + aa;
                float4 va = *(const float4*)&v_s[o * 16 + a * 4];
                float4 q;
                q.x = va.x*w0.x + va.y*w0.y + va.z*w0.z + va.w*w0.w;
                q.y = va.x*w1.x + va.y*w1.y + va.z*w1.z + va.w*w1.w;
                q.z = va.x*w2.x + va.y*w2.y + va.z*w2.z + va.w*w2.w;
                q.w = va.x*w3.x + va.y*w3.y + va.z*w3.z + va.w*w3.w;
                *(float4*)&PQ[(i * 16 + o) * 16 + a * 4] = q;
            }
        }
        __syncthreads();

        // ---- F: logits[ki][o] += dot16(pose[ki], Q[i][o]) ----
        for (int idx = tid; idx < KKI * NOUT; idx += NTHREADS) {
            int ki = idx >> 4;
            int o  = idx & 15;
            int i  = ki & 7;
            const float4* pr = (const float4*)&pose_s[ki * 16];
            const float4* qr = (const float4*)&PQ[(i * 16 + o) * 16];
            float d = 0.0f;
            #pragma unroll
            for (int j = 0; j < 4; j++) {
                float4 p = pr[j], q = qr[j];
                d += p.x*q.x + p.y*q.y + p.z*q.z + p.w*q.w;
            }
            logits[idx] += d;
        }
        __syncthreads();
    }

    // ---- write output: out[n][o][e], o = tid>>4, e = tid&15 ----
    out[(size_t)n * 256 + tid] = vout;
}

extern "C" void kernel_launch(void* const* d_in, const int* in_sizes, int n_in,
                              void* d_out, int out_size)
{
    const float* x = (const float*)d_in[0];
    const float* W = (const float*)d_in[1];
    // Defensive: W has exactly 2048 elements; input has 626688.
    if (n_in >= 2 && in_sizes[0] == 2048) {
        const float* t = x; x = W; W = t;
    }
    float* out = (float*)d_out;
    const int nblocks = 2 * HO * WO;  // 4232
    capsule_kernel<<<nblocks, NTHREADS>>>(x, W, out);
}

// round 4
// speedup vs baseline: 2.1360x; 2.1360x over previous
#include <cuda_runtime.h>

// ConvCapsuleLayer: B=2, H=W=48, IN_CAPS=8, ATOMS=16, KER=3, OUT_CAPS=16, ROUTINGS=3
// Ho=Wo=46, N = 4232 positions. One CTA (128 threads) per position.
//
// Thread mapping for the heavy phases: thread = (i = tid>>4, o = tid&15).
// Within a warp this gives 2 i-values x 16 o-values, so pose[ki] loads are
// 2-distinct-address broadcasts (near-free on the smem crossbar), which was
// the dominant cost of the previous version.
//
// Phases per routing iteration:
//   A: coup[ki][o] = softmax_o(logits[ki]) * act[ki]           (72 threads)
//   B: P[i,o][e]   = sum_k coup[k*8+i][o] * pose[k*8+i][e]     (regs -> smem)
//   C: s[o][a*4+c] = sum_i sum_b P[i,o][a*4+b] * W[i,o][b*4+c] (64 threads)
//   D: v = squash(s)   (shfl_xor reduction, 128 threads)
//   E+F fused: Q[i,o] = f(v[o], W[i,o]) in regs, then
//              logits[k*8+i][o] += dot16(pose[k*8+i], Q)       (no Q in smem)

#define HH 48
#define WW 48
#define CIN 136
#define HO 46
#define WO 46
#define NTH 128
#define ROUTINGS 3

#define DOT4(p, q) ((p).x*(q).x + (p).y*(q).y + (p).z*(q).z + (p).w*(q).w)

__global__ __launch_bounds__(NTH)
void capsule_kernel(const float* __restrict__ x,
                    const float* __restrict__ Wg,
                    float* __restrict__ out)
{
    __shared__ __align__(16) float W_s[128 * 20];    // [(i*16+o)*20 + b*4+c], padded
    __shared__ __align__(16) float P_s[128 * 20];    // [(i*16+o)*20 + e], padded
    __shared__ __align__(16) float pose_s[72 * 16];  // [ki][a*4+b]
    __shared__ float act_s[72];
    __shared__ float logits[72 * 17];                // stride 17: conflict-free scalars
    __shared__ float coup[72 * 17];
    __shared__ __align__(16) float s_s[16 * 16];
    __shared__ __align__(16) float v_s[16 * 16];

    const int tid = threadIdx.x;
    const int n   = blockIdx.x;
    const int b   = n / (HO * WO);
    const int rem = n % (HO * WO);
    const int ho  = rem / WO;
    const int wo  = rem % WO;

    const int i_ = tid >> 4;   // 0..7
    const int o_ = tid & 15;   // 0..15

    // ---- load W into padded layout ----
    #pragma unroll
    for (int idx = tid; idx < 2048; idx += NTH)
        W_s[(idx >> 4) * 20 + (idx & 15)] = Wg[idx];

    // ---- load pose + act ----
    for (int idx = tid; idx < 72 * 17; idx += NTH) {
        int ki = idx / 17;
        int a  = idx - ki * 17;
        int k  = ki >> 3;
        int i  = ki & 7;
        int di = k / 3;
        int dj = k - di * 3;
        float val = x[(size_t)(((b * HH + ho + di) * WW) + (wo + dj)) * CIN + i * 17 + a];
        if (a < 16) pose_s[ki * 16 + a] = val;
        else        act_s[ki] = val;
    }
    for (int idx = tid; idx < 72 * 16; idx += NTH)
        logits[(idx >> 4) * 17 + (idx & 15)] = 0.0f;
    __syncthreads();

    #pragma unroll 1
    for (int r = 0; r < ROUTINGS; r++) {
        // ---- A: coup = softmax(logits) * act ----
        if (tid < 72) {
            const int base = tid * 17;
            float l[16];
            float m = -1e30f;
            #pragma unroll
            for (int o = 0; o < 16; o++) { l[o] = logits[base + o]; m = fmaxf(m, l[o]); }
            float sum = 0.0f;
            #pragma unroll
            for (int o = 0; o < 16; o++) { l[o] = __expf(l[o] - m); sum += l[o]; }
            float scale = act_s[tid] / sum;
            #pragma unroll
            for (int o = 0; o < 16; o++) coup[base + o] = l[o] * scale;
        }
        __syncthreads();

        // ---- B: P[i_,o_][e] = sum_k coup[k*8+i_][o_] * pose[k*8+i_][e] ----
        {
            float4 P0 = make_float4(0.f,0.f,0.f,0.f);
            float4 P1 = make_float4(0.f,0.f,0.f,0.f);
            float4 P2 = make_float4(0.f,0.f,0.f,0.f);
            float4 P3 = make_float4(0.f,0.f,0.f,0.f);
            #pragma unroll
            for (int k = 0; k < 9; k++) {
                const int ki = k * 8 + i_;
                const float c = coup[ki * 17 + o_];
                const float4* pr = (const float4*)&pose_s[ki * 16];  // broadcast
                float4 p0 = pr[0], p1 = pr[1], p2 = pr[2], p3 = pr[3];
                P0.x += c*p0.x; P0.y += c*p0.y; P0.z += c*p0.z; P0.w += c*p0.w;
                P1.x += c*p1.x; P1.y += c*p1.y; P1.z += c*p1.z; P1.w += c*p1.w;
                P2.x += c*p2.x; P2.y += c*p2.y; P2.z += c*p2.z; P2.w += c*p2.w;
                P3.x += c*p3.x; P3.y += c*p3.y; P3.z += c*p3.z; P3.w += c*p3.w;
            }
            float4* dst = (float4*)&P_s[tid * 20];
            dst[0] = P0; dst[1] = P1; dst[2] = P2; dst[3] = P3;
        }
        __syncthreads();

        // ---- C: s[o][a*4+c] = sum_i sum_b P[i,o][a*4+b] * W[i,o][b*4+c] ----
        if (tid < 64) {
            const int o = tid >> 2, a = tid & 3;
            float4 acc = make_float4(0.f,0.f,0.f,0.f);
            #pragma unroll
            for (int i = 0; i < 8; i++) {
                const int row = (i * 16 + o) * 20;
                float4 p = *(const float4*)&P_s[row + a * 4];
                const float4* wr = (const float4*)&W_s[row];
                float4 w0 = wr[0], w1 = wr[1], w2 = wr[2], w3 = wr[3];
                acc.x += p.x*w0.x + p.y*w1.x + p.z*w2.x + p.w*w3.x;
                acc.y += p.x*w0.y + p.y*w1.y + p.z*w2.y + p.w*w3.y;
                acc.z += p.x*w0.z + p.y*w1.z + p.z*w2.z + p.w*w3.z;
                acc.w += p.x*w0.w + p.y*w1.w + p.z*w2.w + p.w*w3.w;
            }
            *(float4*)&s_s[o * 16 + a * 4] = acc;
        }
        __syncthreads();

        // ---- D: squash via shuffle reduction. thread -> (o = tid>>3, pair g = tid&7) ----
        {
            const int o = tid >> 3, g = tid & 7;
            float2 sv = *(const float2*)&s_s[o * 16 + g * 2];
            float part = sv.x * sv.x + sv.y * sv.y;
            part += __shfl_xor_sync(0xffffffffu, part, 1);
            part += __shfl_xor_sync(0xffffffffu, part, 2);
            part += __shfl_xor_sync(0xffffffffu, part, 4);
            const float sq = part;
            const float scale = (sq / (1.0f + sq)) * rsqrtf(sq + 1e-7f);
            float2 vv = make_float2(sv.x * scale, sv.y * scale);
            if (r == ROUTINGS - 1) {
                *(float2*)&out[(size_t)n * 256 + tid * 2] = vv;
            } else {
                *(float2*)&v_s[o * 16 + g * 2] = vv;
            }
        }
        if (r == ROUTINGS - 1) break;
        __syncthreads();

        // ---- E+F fused: Q[a*4+b] = sum_c v[o_][a*4+c] * W[i_,o_][b*4+c]; ----
        // ----            logits[k*8+i_][o_] += sum_{a,b} pose[..][a*4+b]*Q[a*4+b] ----
        {
            const float4* vr = (const float4*)&v_s[o_ * 16];
            float4 v0 = vr[0], v1 = vr[1], v2 = vr[2], v3 = vr[3];
            const float4* wr = (const float4*)&W_s[tid * 20];
            float4 w0 = wr[0], w1 = wr[1], w2 = wr[2], w3 = wr[3];
            float4 Q0, Q1, Q2, Q3;   // Qa.{x..w} = Q[a][b], b = x..w
            Q0.x = DOT4(v0,w0); Q0.y = DOT4(v0,w1); Q0.z = DOT4(v0,w2); Q0.w = DOT4(v0,w3);
            Q1.x = DOT4(v1,w0); Q1.y = DOT4(v1,w1); Q1.z = DOT4(v1,w2); Q1.w = DOT4(v1,w3);
            Q2.x = DOT4(v2,w0); Q2.y = DOT4(v2,w1); Q2.z = DOT4(v2,w2); Q2.w = DOT4(v2,w3);
            Q3.x = DOT4(v3,w0); Q3.y = DOT4(v3,w1); Q3.z = DOT4(v3,w2); Q3.w = DOT4(v3,w3);
            #pragma unroll
            for (int k = 0; k < 9; k++) {
                const int ki = k * 8 + i_;
                const float4* pr = (const float4*)&pose_s[ki * 16];  // broadcast
                float4 p0 = pr[0], p1 = pr[1], p2 = pr[2], p3 = pr[3];
                float d = DOT4(p0, Q0) + DOT4(p1, Q1) + DOT4(p2, Q2) + DOT4(p3, Q3);
                logits[ki * 17 + o_] += d;   // exclusive writer for (ki, o_)
            }
        }
        __syncthreads();
    }
}

extern "C" void kernel_launch(void* const* d_in, const int* in_sizes, int n_in,
                              void* d_out, int out_size)
{
    const float* x = (const float*)d_in[0];
    const float* W = (const float*)d_in[1];
    if (n_in >= 2 && in_sizes[0] == 2048) {   // defensive: W has 2048 elems
        const float* t = x; x = W; W = t;
    }
    float* out = (float*)d_out;
    capsule_kernel<<<2 * HO * WO, NTH>>>(x, W, out);
}

// round 5
// speedup vs baseline: 2.2836x; 1.0691x over previous
#include <cuda_runtime.h>

// ConvCapsuleLayer: B=2, H=W=48, IN_CAPS=8, ATOMS=16, KER=3, OUT_CAPS=16, ROUTINGS=3
// Ho=Wo=46, N = 4232 positions. One CTA (128 threads) per position.
//
// Thread = (i = tid>>4, o = tid&15). W[i,o] (16 floats) lives in REGISTERS for
// the whole kernel; P[i,o] accumulates in registers and feeds a register 4x4
// matmul. The i-reduction for s[o] uses shfl_xor(16) (pairs i within a warp)
// plus a 4-warp partial buffer. Shared memory only carries: pose (warp-
// broadcast reads), coup/logits scalars, the s-partials, and v.

#define HH 48
#define WW 48
#define CIN 136
#define HO 46
#define WO 46
#define NTH 128
#define ROUTINGS 3

#define DOT4(p, q) ((p).x*(q).x + (p).y*(q).y + (p).z*(q).z + (p).w*(q).w)

__global__ __launch_bounds__(NTH)
void capsule_kernel(const float* __restrict__ x,
                    const float* __restrict__ Wg,
                    float* __restrict__ out)
{
    __shared__ __align__(16) float pose_s[72 * 16];  // [ki][a*4+b]
    __shared__ float act_s[72];
    __shared__ float logits[72 * 17];                // stride 17: conflict-free scalars
    __shared__ float coup[72 * 17];
    __shared__ __align__(16) float spart[4][16 * 20]; // [warp][o*20 + e], padded
    __shared__ __align__(16) float v_s[16 * 16];      // [o][e]

    const int tid = threadIdx.x;
    const int n   = blockIdx.x;
    const int b   = n / (HO * WO);
    const int rem = n % (HO * WO);
    const int ho  = rem / WO;
    const int wo  = rem % WO;

    const int i_ = tid >> 4;   // 0..7
    const int o_ = tid & 15;   // 0..15
    const int wrp = tid >> 5;  // 0..3

    // ---- W[i_,o_] into registers (coalesced: warp reads 2KB contiguous) ----
    const float4* wg = (const float4*)&Wg[tid * 16];
    const float4 w0 = wg[0], w1 = wg[1], w2 = wg[2], w3 = wg[3];

    // ---- load pose + act ----
    for (int idx = tid; idx < 72 * 17; idx += NTH) {
        int ki = idx / 17;
        int a  = idx - ki * 17;
        int k  = ki >> 3;
        int i  = ki & 7;
        int di = k / 3;
        int dj = k - di * 3;
        float val = x[(size_t)(((b * HH + ho + di) * WW) + (wo + dj)) * CIN + i * 17 + a];
        if (a < 16) pose_s[ki * 16 + a] = val;
        else        act_s[ki] = val;
    }
    for (int idx = tid; idx < 72 * 16; idx += NTH)
        logits[(idx >> 4) * 17 + (idx & 15)] = 0.0f;
    __syncthreads();

    #pragma unroll 1
    for (int r = 0; r < ROUTINGS; r++) {
        // ---- A: coup = softmax_o(logits) * act ----
        if (tid < 72) {
            const int base = tid * 17;
            float l[16];
            float m = -1e30f;
            #pragma unroll
            for (int o = 0; o < 16; o++) { l[o] = logits[base + o]; m = fmaxf(m, l[o]); }
            float sum = 0.0f;
            #pragma unroll
            for (int o = 0; o < 16; o++) { l[o] = __expf(l[o] - m); sum += l[o]; }
            float scale = act_s[tid] / sum;
            #pragma unroll
            for (int o = 0; o < 16; o++) coup[base + o] = l[o] * scale;
        }
        __syncthreads();

        // ---- B: P[i_,o_][e] = sum_k coup[k*8+i_][o_] * pose[k*8+i_][e] (regs) ----
        float4 P0 = make_float4(0.f,0.f,0.f,0.f);
        float4 P1 = make_float4(0.f,0.f,0.f,0.f);
        float4 P2 = make_float4(0.f,0.f,0.f,0.f);
        float4 P3 = make_float4(0.f,0.f,0.f,0.f);
        #pragma unroll
        for (int k = 0; k < 9; k++) {
            const int ki = k * 8 + i_;
            const float c = coup[ki * 17 + o_];
            const float4* pr = (const float4*)&pose_s[ki * 16];  // 2-addr broadcast
            float4 p0 = pr[0], p1 = pr[1], p2 = pr[2], p3 = pr[3];
            P0.x += c*p0.x; P0.y += c*p0.y; P0.z += c*p0.z; P0.w += c*p0.w;
            P1.x += c*p1.x; P1.y += c*p1.y; P1.z += c*p1.z; P1.w += c*p1.w;
            P2.x += c*p2.x; P2.y += c*p2.y; P2.z += c*p2.z; P2.w += c*p2.w;
            P3.x += c*p3.x; P3.y += c*p3.y; P3.z += c*p3.z; P3.w += c*p3.w;
        }

        // ---- C: M = P @ W (registers), reduce over i via shfl + 4-warp partials ----
        {
            float4 M0, M1, M2, M3;  // Ma.{x..w} = s-contrib[a][c=0..3]
            M0.x = P0.x*w0.x + P0.y*w1.x + P0.z*w2.x + P0.w*w3.x;
            M0.y = P0.x*w0.y + P0.y*w1.y + P0.z*w2.y + P0.w*w3.y;
            M0.z = P0.x*w0.z + P0.y*w1.z + P0.z*w2.z + P0.w*w3.z;
            M0.w = P0.x*w0.w + P0.y*w1.w + P0.z*w2.w + P0.w*w3.w;
            M1.x = P1.x*w0.x + P1.y*w1.x + P1.z*w2.x + P1.w*w3.x;
            M1.y = P1.x*w0.y + P1.y*w1.y + P1.z*w2.y + P1.w*w3.y;
            M1.z = P1.x*w0.z + P1.y*w1.z + P1.z*w2.z + P1.w*w3.z;
            M1.w = P1.x*w0.w + P1.y*w1.w + P1.z*w2.w + P1.w*w3.w;
            M2.x = P2.x*w0.x + P2.y*w1.x + P2.z*w2.x + P2.w*w3.x;
            M2.y = P2.x*w0.y + P2.y*w1.y + P2.z*w2.y + P2.w*w3.y;
            M2.z = P2.x*w0.z + P2.y*w1.z + P2.z*w2.z + P2.w*w3.z;
            M2.w = P2.x*w0.w + P2.y*w1.w + P2.z*w2.w + P2.w*w3.w;
            M3.x = P3.x*w0.x + P3.y*w1.x + P3.z*w2.x + P3.w*w3.x;
            M3.y = P3.x*w0.y + P3.y*w1.y + P3.z*w2.y + P3.w*w3.y;
            M3.z = P3.x*w0.z + P3.y*w1.z + P3.z*w2.z + P3.w*w3.z;
            M3.w = P3.x*w0.w + P3.y*w1.w + P3.z*w2.w + P3.w*w3.w;

            // pair-reduce over i within warp (lane^16 flips i bit 0)
            #define XR(f) f += __shfl_xor_sync(0xffffffffu, f, 16)
            XR(M0.x); XR(M0.y); XR(M0.z); XR(M0.w);
            XR(M1.x); XR(M1.y); XR(M1.z); XR(M1.w);
            XR(M2.x); XR(M2.y); XR(M2.z); XR(M2.w);
            XR(M3.x); XR(M3.y); XR(M3.z); XR(M3.w);
            #undef XR

            // split store: even-i lanes store e[0..7], odd-i lanes e[8..15]
            float4* dst = (float4*)&spart[wrp][o_ * 20];
            if ((tid & 16) == 0) { dst[0] = M0; dst[1] = M1; }
            else                 { dst[2] = M2; dst[3] = M3; }
        }
        __syncthreads();

        // ---- D: s[o][e] = sum_w spart[w][o][e]; squash; write v or out ----
        {
            const int o = tid >> 3, g = tid & 7;
            const int off = o * 20 + g * 2;
            float2 a0 = *(const float2*)&spart[0][off];
            float2 a1 = *(const float2*)&spart[1][off];
            float2 a2 = *(const float2*)&spart[2][off];
            float2 a3 = *(const float2*)&spart[3][off];
            float2 sv = make_float2(a0.x + a1.x + a2.x + a3.x,
                                    a0.y + a1.y + a2.y + a3.y);
            float part = sv.x * sv.x + sv.y * sv.y;
            part += __shfl_xor_sync(0xffffffffu, part, 1);
            part += __shfl_xor_sync(0xffffffffu, part, 2);
            part += __shfl_xor_sync(0xffffffffu, part, 4);
            const float sq = part;
            const float scale = (sq / (1.0f + sq)) * rsqrtf(sq + 1e-7f);
            float2 vv = make_float2(sv.x * scale, sv.y * scale);
            if (r == ROUTINGS - 1) {
                *(float2*)&out[(size_t)n * 256 + tid * 2] = vv;
            } else {
                *(float2*)&v_s[o * 16 + g * 2] = vv;
            }
        }
        if (r == ROUTINGS - 1) break;
        __syncthreads();

        // ---- E+F fused: Q = f(v[o_], Wreg); logits[k*8+i_][o_] += dot16(pose, Q) ----
        {
            const float4* vr = (const float4*)&v_s[o_ * 16];
            float4 v0 = vr[0], v1 = vr[1], v2 = vr[2], v3 = vr[3];
            float4 Q0, Q1, Q2, Q3;   // Qa.{x..w} = Q[a][b]
            Q0.x = DOT4(v0,w0); Q0.y = DOT4(v0,w1); Q0.z = DOT4(v0,w2); Q0.w = DOT4(v0,w3);
            Q1.x = DOT4(v1,w0); Q1.y = DOT4(v1,w1); Q1.z = DOT4(v1,w2); Q1.w = DOT4(v1,w3);
            Q2.x = DOT4(v2,w0); Q2.y = DOT4(v2,w1); Q2.z = DOT4(v2,w2); Q2.w = DOT4(v2,w3);
            Q3.x = DOT4(v3,w0); Q3.y = DOT4(v3,w1); Q3.z = DOT4(v3,w2); Q3.w = DOT4(v3,w3);
            #pragma unroll
            for (int k = 0; k < 9; k++) {
                const int ki = k * 8 + i_;
                const float4* pr = (const float4*)&pose_s[ki * 16];  // broadcast
                float4 p0 = pr[0], p1 = pr[1], p2 = pr[2], p3 = pr[3];
                float d = DOT4(p0, Q0) + DOT4(p1, Q1) + DOT4(p2, Q2) + DOT4(p3, Q3);
                logits[ki * 17 + o_] += d;   // exclusive writer for (ki, o_)
            }
        }
        __syncthreads();
    }
}

extern "C" void kernel_launch(void* const* d_in, const int* in_sizes, int n_in,
                              void* d_out, int out_size)
{
    const float* x = (const float*)d_in[0];
    const float* W = (const float*)d_in[1];
    if (n_in >= 2 && in_sizes[0] == 2048) {   // defensive: W has 2048 elems
        const float* t = x; x = W; W = t;
    }
    float* out = (float*)d_out;
    capsule_kernel<<<2 * HO * WO, NTH>>>(x, W, out);
}